// round 1
// baseline (speedup 1.0000x reference)
#include <cuda_runtime.h>

// Pendulum2 constrained-dynamics RHS, closed form.
// In : coords (bs, 8) fp32  [x0 x1 x2 x3 v0 v1 v2 v3]
// Out: (bs, 8) fp32         [v0 v1 v2 v3 a0 a1 a2 a3]
//
// Derivation (M0=M1=10, G=10):
//   phi_q = [[2x0, 2x1, 0, 0], [2dx, 2dy, -2dx, -2dy]]
//   L = phi_q Minv phi_q^T = 0.4*[[s1, c],[c, 2 s2]]
//   det' = 2 s1 s2 - c^2 = s1 s2 + u^2   (u = x0 dy - x1 dx; cancellation-free)
//   R1 = -20 x1 + 2(v0^2+v1^2); R2 = 2(dv0^2+dv1^2)   (gravity row-2 term cancels)
//   lam = 2.5 * adj([[s1,c],[c,2s2]]) R / det'
//   a = (F - phi_q^T lam)/10

__global__ void __launch_bounds__(256)
pendulum2_kernel(const float4* __restrict__ in4, float4* __restrict__ out4, int bs)
{
    int i = blockIdx.x * blockDim.x + threadIdx.x;
    if (i >= bs) return;

    float4 X = in4[2 * i];       // x0 x1 x2 x3
    float4 V = in4[2 * i + 1];   // v0 v1 v2 v3

    float dx  = X.x - X.z;
    float dy  = X.y - X.w;
    float dv0 = V.x - V.z;
    float dv1 = V.y - V.w;

    float s1 = fmaf(X.x, X.x, X.y * X.y);
    float s2 = fmaf(dx, dx, dy * dy);
    float c  = fmaf(X.x, dx, X.y * dy);
    float u  = fmaf(X.x, dy, -(X.y * dx));

    float R1 = fmaf(2.0f, fmaf(V.x, V.x, V.y * V.y), -20.0f * X.y);
    float R2 = 2.0f * fmaf(dv0, dv0, dv1 * dv1);

    float det  = fmaf(s1, s2, u * u);      // = 2*s1*s2 - c^2, stable form
    float inv  = 2.5f / det;

    float lam1 = (fmaf(2.0f * s2, R1, -(c * R2))) * inv;
    float lam2 = (fmaf(s1, R2, -(c * R1))) * inv;

    float4 A;
    A.x = -0.2f * fmaf(X.x, lam1, dx * lam2);
    A.y = fmaf(-0.2f, fmaf(X.y, lam1, dy * lam2), -10.0f);
    A.z = 0.2f * (dx * lam2);
    A.w = fmaf(0.2f, dy * lam2, -10.0f);

    out4[2 * i]     = V;
    out4[2 * i + 1] = A;
}

extern "C" void kernel_launch(void* const* d_in, const int* in_sizes, int n_in,
                              void* d_out, int out_size)
{
    // inputs (metadata order): t (1,), coords (bs, 8)
    const float* coords = (const float*)d_in[1];
    int bs = in_sizes[1] / 8;

    const float4* in4 = (const float4*)coords;
    float4* out4      = (float4*)d_out;

    int threads = 256;
    int blocks  = (bs + threads - 1) / threads;
    pendulum2_kernel<<<blocks, threads>>>(in4, out4, bs);
}